// round 3
// baseline (speedup 1.0000x reference)
#include <cuda_runtime.h>
#include <math.h>

#define BB   64
#define TT   512
#define IND  256
#define HH   1024
#define OUTD 256

#define NCTA  128
#define COLS  8            // H columns per CTA
#define KW    128          // K chunk per warp (8 warps)
#define WSTR  1025         // padded smem weight stride

// -------- device scratch (static allocations only) --------
__device__ float g_xh[TT * BB * HH];   // [t][j][b]
__device__ float g_xz[TT * BB * HH];
__device__ float g_xr[TT * BB * HH];
__device__ float g_hT [HH * BB];       // h   [k][b]
__device__ float g_hrT[HH * BB];       // h*r [k][b]
__device__ unsigned g_bar_cnt;
__device__ volatile unsigned g_bar_gen;

// -------- grid-wide sense-reversing barrier --------
// __threadfence (gpu scope) emits CCTL.IVALL on sm_103a: flushes L1D so
// peer-CTA writes are not read stale after the barrier.
__device__ __forceinline__ void grid_sync() {
    __syncthreads();
    if (threadIdx.x == 0) {
        __threadfence();
        unsigned gen = g_bar_gen;
        if (atomicAdd(&g_bar_cnt, 1u) == gridDim.x - 1u) {
            g_bar_cnt = 0u;
            __threadfence();
            g_bar_gen = gen + 1u;
        } else {
            while (g_bar_gen == gen) { __nanosleep(32); }
        }
        __threadfence();
    }
    __syncthreads();
}

__device__ __forceinline__ float sigm_(float x) { return 1.0f / (1.0f + __expf(-x)); }

// -------- kernel 1: input projections (Wx, Uz, Ur) --------
// out[t][j][b] = sum_i X[b][t][i] * W[j][i] + bias[j]
__global__ __launch_bounds__(256) void proj_kernel(
    const float* __restrict__ X,
    const float* __restrict__ W0, const float* __restrict__ W1, const float* __restrict__ W2,
    const float* __restrict__ b0, const float* __restrict__ b1, const float* __restrict__ b2)
{
    __shared__ float As[64][33];
    __shared__ float Bs[64][33];

    const int z = blockIdx.z;
    const float* W    = (z == 0) ? W0 : (z == 1) ? W1 : W2;
    const float* bias = (z == 0) ? b0 : (z == 1) ? b1 : b2;
    float*       outp = (z == 0) ? g_xh : (z == 1) ? g_xz : g_xr;

    const int t   = blockIdx.y;
    const int j0  = blockIdx.x * 64;
    const int tid = threadIdx.x;
    const int ty  = tid >> 4;
    const int tx  = tid & 15;

    float acc[4][4];
#pragma unroll
    for (int i = 0; i < 4; i++)
#pragma unroll
        for (int ii = 0; ii < 4; ii++) acc[i][ii] = 0.0f;

    for (int kt = 0; kt < IND; kt += 32) {
#pragma unroll
        for (int l = 0; l < 8; l++) {
            int flat = tid + l * 256;
            int row = flat >> 5, col = flat & 31;
            As[row][col] = W[(j0 + row) * IND + kt + col];
            Bs[row][col] = X[row * (TT * IND) + t * IND + kt + col];
        }
        __syncthreads();
#pragma unroll
        for (int kk = 0; kk < 32; kk++) {
            float a[4], bv[4];
#pragma unroll
            for (int i = 0; i < 4; i++)  a[i]  = As[ty * 4 + i][kk];
#pragma unroll
            for (int ii = 0; ii < 4; ii++) bv[ii] = Bs[tx * 4 + ii][kk];
#pragma unroll
            for (int i = 0; i < 4; i++)
#pragma unroll
                for (int ii = 0; ii < 4; ii++)
                    acc[i][ii] += a[i] * bv[ii];
        }
        __syncthreads();
    }
#pragma unroll
    for (int i = 0; i < 4; i++) {
        int j = j0 + ty * 4 + i;
        float bvv = bias[j];
        float4 v = make_float4(acc[i][0] + bvv, acc[i][1] + bvv,
                               acc[i][2] + bvv, acc[i][3] + bvv);
        *reinterpret_cast<float4*>(&outp[t * (HH * BB) + j * BB + tx * 4]) = v;
    }
}

// -------- kernel 2: persistent scan --------
__global__ __launch_bounds__(256, 1) void scan_kernel(
    const float* __restrict__ Wh,
    const float* __restrict__ Vz,
    const float* __restrict__ Vr)
{
    extern __shared__ float smem[];
    float* w_s  = smem;                        // 3*COLS*WSTR
    float* redz = smem + 3 * COLS * WSTR;      // 8*512
    float* redr = redz + 8 * 512;              // 8*512

    const int tid  = threadIdx.x;
    const int j0   = blockIdx.x * COLS;
    const int warp = tid >> 5;
    const int lane = tid & 31;
    const int b4   = (lane >> 1) * 4;          // 4 consecutive batches
    const int js   = (lane & 1) * 4;           // 4 local columns

    // persistent weights -> smem
    {
        const float* srcs[3] = { Wh, Vz, Vr };
        for (int g = 0; g < 3; g++) {
            const float* S = srcs[g];
            for (int idx = tid; idx < COLS * HH; idx += 256) {
                int jj = idx >> 10, k = idx & 1023;
                w_s[(g * COLS + jj) * WSTR + k] = S[(j0 + jj) * HH + k];
            }
        }
    }

    // per-thread state: 2 elements, e = 2*tid = my_jj*64 + my_b
    const int my_jj = tid >> 5;
    const int my_b  = (2 * tid) & 63;
    float h0 = 0.f, h1 = 0.f, z0 = 0.f, z1 = 0.f;

    *reinterpret_cast<float2*>(&g_hrT[(j0 + my_jj) * BB + my_b]) = make_float2(0.f, 0.f);
    grid_sync();

    const int kbeg = warp * KW;
    const int kend = kbeg + KW;

    for (int t = 0; t < TT; t++) {
        const int xofs = t * (HH * BB) + (j0 + my_jj) * BB + my_b;
        float2 xh = *reinterpret_cast<const float2*>(&g_xh[xofs]);
        float2 xz = *reinterpret_cast<const float2*>(&g_xz[xofs]);
        float2 xr = *reinterpret_cast<const float2*>(&g_xr[xofs]);

        // ---- phase 1: (h*r) @ Wh^T, then h update
        {
            float acc[4][4];
#pragma unroll
            for (int x = 0; x < 4; x++)
#pragma unroll
                for (int y = 0; y < 4; y++) acc[x][y] = 0.f;
            const float* wb = w_s + js * WSTR;
#pragma unroll 4
            for (int k = kbeg; k < kend; k++) {
                float4 a = *reinterpret_cast<const float4*>(&g_hrT[k * BB + b4]);
                float av[4] = { a.x, a.y, a.z, a.w };
#pragma unroll
                for (int x = 0; x < 4; x++) {
                    float wv = wb[x * WSTR + k];
#pragma unroll
                    for (int y = 0; y < 4; y++) acc[x][y] += wv * av[y];
                }
            }
#pragma unroll
            for (int x = 0; x < 4; x++)
                *reinterpret_cast<float4*>(&redz[warp * 512 + (js + x) * 64 + b4]) =
                    make_float4(acc[x][0], acc[x][1], acc[x][2], acc[x][3]);
        }
        __syncthreads();
        {
            int e = 2 * tid;
            float s0 = 0.f, s1 = 0.f;
#pragma unroll
            for (int w = 0; w < 8; w++) {
                float2 v = *reinterpret_cast<const float2*>(&redz[w * 512 + e]);
                s0 += v.x; s1 += v.y;
            }
            float ht0 = tanhf(xh.x + s0);
            float ht1 = tanhf(xh.y + s1);
            h0 = z0 * h0 + (1.f - z0) * ht0;
            h1 = z1 * h1 + (1.f - z1) * ht1;
            *reinterpret_cast<float2*>(&g_hT[(j0 + my_jj) * BB + my_b]) = make_float2(h0, h1);
        }
        grid_sync();

        // ---- phase 2: h @ Vz^T, h @ Vr^T; z, r, hr
        {
            float az[4][4], ar[4][4];
#pragma unroll
            for (int x = 0; x < 4; x++)
#pragma unroll
                for (int y = 0; y < 4; y++) { az[x][y] = 0.f; ar[x][y] = 0.f; }
            const float* wzb = w_s + (COLS + js) * WSTR;
            const float* wrb = w_s + (2 * COLS + js) * WSTR;
#pragma unroll 4
            for (int k = kbeg; k < kend; k++) {
                float4 a = *reinterpret_cast<const float4*>(&g_hT[k * BB + b4]);
                float av[4] = { a.x, a.y, a.z, a.w };
#pragma unroll
                for (int x = 0; x < 4; x++) {
                    float wz = wzb[x * WSTR + k];
                    float wr = wrb[x * WSTR + k];
#pragma unroll
                    for (int y = 0; y < 4; y++) {
                        az[x][y] += wz * av[y];
                        ar[x][y] += wr * av[y];
                    }
                }
            }
#pragma unroll
            for (int x = 0; x < 4; x++) {
                *reinterpret_cast<float4*>(&redz[warp * 512 + (js + x) * 64 + b4]) =
                    make_float4(az[x][0], az[x][1], az[x][2], az[x][3]);
                *reinterpret_cast<float4*>(&redr[warp * 512 + (js + x) * 64 + b4]) =
                    make_float4(ar[x][0], ar[x][1], ar[x][2], ar[x][3]);
            }
        }
        __syncthreads();
        {
            int e = 2 * tid;
            float sz0 = 0.f, sz1 = 0.f, sr0 = 0.f, sr1 = 0.f;
#pragma unroll
            for (int w = 0; w < 8; w++) {
                float2 vz = *reinterpret_cast<const float2*>(&redz[w * 512 + e]);
                float2 vr = *reinterpret_cast<const float2*>(&redr[w * 512 + e]);
                sz0 += vz.x; sz1 += vz.y;
                sr0 += vr.x; sr1 += vr.y;
            }
            z0 = sigm_(xz.x + sz0);
            z1 = sigm_(xz.y + sz1);
            float r0 = sigm_(xr.x + sr0);
            float r1 = sigm_(xr.y + sr1);
            *reinterpret_cast<float2*>(&g_hrT[(j0 + my_jj) * BB + my_b]) =
                make_float2(h0 * r0, h1 * r1);
        }
        grid_sync();
    }
}

// -------- kernel 3: output projection out[b][o] = h @ Wo^T + bo --------
__global__ __launch_bounds__(256) void out_kernel(
    const float* __restrict__ Wo, const float* __restrict__ bo, float* __restrict__ out)
{
    const int b = threadIdx.x & 63;
    const int o = blockIdx.x * 4 + (threadIdx.x >> 6);
    float s = 0.f;
#pragma unroll 8
    for (int j = 0; j < HH; j++)
        s += g_hT[j * BB + b] * Wo[o * HH + j];
    out[b * OUTD + o] = s + bo[o];
}

extern "C" void kernel_launch(void* const* d_in, const int* in_sizes, int n_in,
                              void* d_out, int out_size) {
    const float* X  = (const float*)d_in[0];
    const float* Wx = (const float*)d_in[1];
    const float* bx = (const float*)d_in[2];
    const float* Wh = (const float*)d_in[3];
    const float* Uz = (const float*)d_in[4];
    const float* bz = (const float*)d_in[5];
    const float* Vz = (const float*)d_in[6];
    const float* Ur = (const float*)d_in[7];
    const float* br = (const float*)d_in[8];
    const float* Vr = (const float*)d_in[9];
    const float* Wo = (const float*)d_in[10];
    const float* bo = (const float*)d_in[11];
    float* out = (float*)d_out;

    const int scan_smem = (3 * COLS * WSTR + 2 * 8 * 512) * (int)sizeof(float);
    cudaFuncSetAttribute(scan_kernel, cudaFuncAttributeMaxDynamicSharedMemorySize, scan_smem);

    dim3 pg(HH / 64, TT, 3);
    proj_kernel<<<pg, 256>>>(X, Wx, Uz, Ur, bx, bz, br);
    scan_kernel<<<NCTA, 256, scan_smem>>>(Wh, Vz, Vr);
    out_kernel<<<OUTD / 4, 256>>>(Wo, bo, out);
}

// round 4
// speedup vs baseline: 1.4766x; 1.4766x over previous
#include <cuda_runtime.h>
#include <math.h>

#define BB   64
#define TT   512
#define IND  256
#define HH   1024
#define OUTD 256

#define NCTA  128
#define COLS  8            // H columns per CTA
#define KW    128          // K chunk per warp (8 warps)

// -------- device scratch --------
__device__ float g_xh[TT * BB * HH];   // [t][j][b]
__device__ float g_xz[TT * BB * HH];
__device__ float g_xr[TT * BB * HH];
__device__ float g_hT [HH * BB];       // h   [k][b]
__device__ float g_hrT[HH * BB];       // h*r [k][b]
__device__ unsigned g_bar_cnt;
__device__ volatile unsigned g_bar_gen;

// -------- f32x2 helpers (packed fp32 pipe, bit-exact fp32) --------
__device__ __forceinline__ unsigned long long splat2(float x) {
    unsigned long long r; asm("mov.b64 %0, {%1, %1};" : "=l"(r) : "f"(x)); return r;
}
__device__ __forceinline__ unsigned long long pack2(float x, float y) {
    unsigned long long r; asm("mov.b64 %0, {%1, %2};" : "=l"(r) : "f"(x), "f"(y)); return r;
}
__device__ __forceinline__ void fma2(unsigned long long& d, unsigned long long a, unsigned long long b) {
    asm("fma.rn.f32x2 %0, %1, %2, %0;" : "+l"(d) : "l"(a), "l"(b));
}
__device__ __forceinline__ void add2(unsigned long long& d, unsigned long long a) {
    asm("add.rn.f32x2 %0, %0, %1;" : "+l"(d) : "l"(a));
}
__device__ __forceinline__ float2 unpack2(unsigned long long v) {
    float2 f; asm("mov.b64 {%0, %1}, %2;" : "=f"(f.x), "=f"(f.y) : "l"(v)); return f;
}

// -------- grid barrier --------
// Consumers of cross-CTA data use ld.global.cg (L2, bypass L1), so no
// acquire-side L1 flush (CCTL.IVALL) is needed. Release fence drains this
// CTA's stores to L2 before the arrive.
__device__ __forceinline__ void grid_sync() {
    __syncthreads();
    if (threadIdx.x == 0) {
        unsigned gen = g_bar_gen;
        __threadfence();                                   // release
        if (atomicAdd(&g_bar_cnt, 1u) == gridDim.x - 1u) {
            g_bar_cnt = 0u;
            __threadfence();                               // reset before gen flip
            g_bar_gen = gen + 1u;
        } else {
            while (g_bar_gen == gen) { __nanosleep(32); }
        }
    }
    __syncthreads();
}

__device__ __forceinline__ float sigm_(float x) { return 1.0f / (1.0f + __expf(-x)); }

// -------- kernel 1: input projections (Wx, Uz, Ur) --------
__global__ __launch_bounds__(256) void proj_kernel(
    const float* __restrict__ X,
    const float* __restrict__ W0, const float* __restrict__ W1, const float* __restrict__ W2,
    const float* __restrict__ b0, const float* __restrict__ b1, const float* __restrict__ b2)
{
    __shared__ float As[64][33];
    __shared__ float Bs[64][33];

    const int z = blockIdx.z;
    const float* W    = (z == 0) ? W0 : (z == 1) ? W1 : W2;
    const float* bias = (z == 0) ? b0 : (z == 1) ? b1 : b2;
    float*       outp = (z == 0) ? g_xh : (z == 1) ? g_xz : g_xr;

    const int t   = blockIdx.y;
    const int j0  = blockIdx.x * 64;
    const int tid = threadIdx.x;
    const int ty  = tid >> 4;
    const int tx  = tid & 15;

    unsigned long long acc2[4][2];
#pragma unroll
    for (int i = 0; i < 4; i++) { acc2[i][0] = 0ull; acc2[i][1] = 0ull; }

    for (int kt = 0; kt < IND; kt += 32) {
#pragma unroll
        for (int l = 0; l < 8; l++) {
            int flat = tid + l * 256;
            int row = flat >> 5, col = flat & 31;
            As[row][col] = W[(j0 + row) * IND + kt + col];
            Bs[row][col] = X[row * (TT * IND) + t * IND + kt + col];
        }
        __syncthreads();
#pragma unroll
        for (int kk = 0; kk < 32; kk++) {
            float a[4], bv[4];
#pragma unroll
            for (int i = 0; i < 4; i++)  a[i]  = As[ty * 4 + i][kk];
#pragma unroll
            for (int ii = 0; ii < 4; ii++) bv[ii] = Bs[tx * 4 + ii][kk];
            unsigned long long b01 = pack2(bv[0], bv[1]);
            unsigned long long b23 = pack2(bv[2], bv[3]);
#pragma unroll
            for (int i = 0; i < 4; i++) {
                unsigned long long aa = splat2(a[i]);
                fma2(acc2[i][0], aa, b01);
                fma2(acc2[i][1], aa, b23);
            }
        }
        __syncthreads();
    }
#pragma unroll
    for (int i = 0; i < 4; i++) {
        int j = j0 + ty * 4 + i;
        float bvv = bias[j];
        float2 p0 = unpack2(acc2[i][0]);
        float2 p1 = unpack2(acc2[i][1]);
        float4 v = make_float4(p0.x + bvv, p0.y + bvv, p1.x + bvv, p1.y + bvv);
        *reinterpret_cast<float4*>(&outp[t * (HH * BB) + j * BB + tx * 4]) = v;
    }
}

// -------- kernel 2: persistent scan --------
// SMEM weights transposed: w_s[g*8192 + k*8 + jj] (8 cols contiguous -> LDS.128)
__global__ __launch_bounds__(256, 1) void scan_kernel(
    const float* __restrict__ Wh,
    const float* __restrict__ Vz,
    const float* __restrict__ Vr)
{
    extern __shared__ float smem[];
    float* w_s  = smem;                    // 3 * 8192 floats
    float* redz = smem + 3 * 8192;         // 8*512
    float* redr = redz + 8 * 512;          // 8*512

    const int tid  = threadIdx.x;
    const int j0   = blockIdx.x * COLS;
    const int warp = tid >> 5;
    const int lane = tid & 31;
    const int b4   = (lane >> 1) * 4;
    const int js   = (lane & 1) * 4;

    {
        const float* srcs[3] = { Wh, Vz, Vr };
        for (int g = 0; g < 3; g++) {
            const float* S = srcs[g];
            for (int idx = tid; idx < COLS * HH; idx += 256) {
                int jj = idx >> 10, k = idx & 1023;
                w_s[g * 8192 + k * 8 + jj] = S[(j0 + jj) * HH + k];
            }
        }
    }

    const int my_jj = tid >> 5;
    const int my_b  = (2 * tid) & 63;
    float h0 = 0.f, h1 = 0.f, z0 = 0.f, z1 = 0.f;

    *reinterpret_cast<float2*>(&g_hrT[(j0 + my_jj) * BB + my_b]) = make_float2(0.f, 0.f);
    grid_sync();

    const int kbeg = warp * KW;
    const int kend = kbeg + KW;

    for (int t = 0; t < TT; t++) {
        const int xofs = t * (HH * BB) + (j0 + my_jj) * BB + my_b;
        float2 xh = *reinterpret_cast<const float2*>(&g_xh[xofs]);
        float2 xz = *reinterpret_cast<const float2*>(&g_xz[xofs]);
        float2 xr = *reinterpret_cast<const float2*>(&g_xr[xofs]);

        // ---- phase 1: (h*r) @ Wh^T
        {
            unsigned long long acc[4][2];
#pragma unroll
            for (int x = 0; x < 4; x++) { acc[x][0] = 0ull; acc[x][1] = 0ull; }
#pragma unroll 8
            for (int k = kbeg; k < kend; k++) {
                float4 a = __ldcg(reinterpret_cast<const float4*>(&g_hrT[k * BB + b4]));
                unsigned long long a01 = pack2(a.x, a.y);
                unsigned long long a23 = pack2(a.z, a.w);
                float4 w = *reinterpret_cast<const float4*>(&w_s[k * 8 + js]);
                float wv[4] = { w.x, w.y, w.z, w.w };
#pragma unroll
                for (int x = 0; x < 4; x++) {
                    unsigned long long w2 = splat2(wv[x]);
                    fma2(acc[x][0], w2, a01);
                    fma2(acc[x][1], w2, a23);
                }
            }
#pragma unroll
            for (int x = 0; x < 4; x++) {
                ulonglong2 st; st.x = acc[x][0]; st.y = acc[x][1];
                *reinterpret_cast<ulonglong2*>(&redz[warp * 512 + (js + x) * 64 + b4]) = st;
            }
        }
        __syncthreads();
        {
            int e = 2 * tid;
            unsigned long long s = 0ull;
#pragma unroll
            for (int w = 0; w < 8; w++)
                add2(s, *reinterpret_cast<const unsigned long long*>(&redz[w * 512 + e]));
            float2 sv = unpack2(s);
            float ht0 = tanhf(xh.x + sv.x);
            float ht1 = tanhf(xh.y + sv.y);
            h0 = z0 * h0 + (1.f - z0) * ht0;
            h1 = z1 * h1 + (1.f - z1) * ht1;
            *reinterpret_cast<float2*>(&g_hT[(j0 + my_jj) * BB + my_b]) = make_float2(h0, h1);
        }
        grid_sync();

        // ---- phase 2: h @ Vz^T, h @ Vr^T
        {
            unsigned long long az[4][2], ar[4][2];
#pragma unroll
            for (int x = 0; x < 4; x++) { az[x][0] = az[x][1] = 0ull; ar[x][0] = ar[x][1] = 0ull; }
#pragma unroll 8
            for (int k = kbeg; k < kend; k++) {
                float4 a = __ldcg(reinterpret_cast<const float4*>(&g_hT[k * BB + b4]));
                unsigned long long a01 = pack2(a.x, a.y);
                unsigned long long a23 = pack2(a.z, a.w);
                float4 wzv = *reinterpret_cast<const float4*>(&w_s[8192 + k * 8 + js]);
                float4 wrv = *reinterpret_cast<const float4*>(&w_s[16384 + k * 8 + js]);
                float wz[4] = { wzv.x, wzv.y, wzv.z, wzv.w };
                float wr[4] = { wrv.x, wrv.y, wrv.z, wrv.w };
#pragma unroll
                for (int x = 0; x < 4; x++) {
                    unsigned long long wz2 = splat2(wz[x]);
                    unsigned long long wr2 = splat2(wr[x]);
                    fma2(az[x][0], wz2, a01);
                    fma2(az[x][1], wz2, a23);
                    fma2(ar[x][0], wr2, a01);
                    fma2(ar[x][1], wr2, a23);
                }
            }
#pragma unroll
            for (int x = 0; x < 4; x++) {
                ulonglong2 sz; sz.x = az[x][0]; sz.y = az[x][1];
                ulonglong2 sr; sr.x = ar[x][0]; sr.y = ar[x][1];
                *reinterpret_cast<ulonglong2*>(&redz[warp * 512 + (js + x) * 64 + b4]) = sz;
                *reinterpret_cast<ulonglong2*>(&redr[warp * 512 + (js + x) * 64 + b4]) = sr;
            }
        }
        __syncthreads();
        {
            int e = 2 * tid;
            unsigned long long sz = 0ull, sr = 0ull;
#pragma unroll
            for (int w = 0; w < 8; w++) {
                add2(sz, *reinterpret_cast<const unsigned long long*>(&redz[w * 512 + e]));
                add2(sr, *reinterpret_cast<const unsigned long long*>(&redr[w * 512 + e]));
            }
            float2 vz = unpack2(sz);
            float2 vr = unpack2(sr);
            z0 = sigm_(xz.x + vz.x);
            z1 = sigm_(xz.y + vz.y);
            float r0 = sigm_(xr.x + vr.x);
            float r1 = sigm_(xr.y + vr.y);
            *reinterpret_cast<float2*>(&g_hrT[(j0 + my_jj) * BB + my_b]) =
                make_float2(h0 * r0, h1 * r1);
        }
        grid_sync();
    }
}

// -------- kernel 3: output projection --------
__global__ __launch_bounds__(256) void out_kernel(
    const float* __restrict__ Wo, const float* __restrict__ bo, float* __restrict__ out)
{
    const int b = threadIdx.x & 63;
    const int o = blockIdx.x * 4 + (threadIdx.x >> 6);
    float s = 0.f;
#pragma unroll 8
    for (int j = 0; j < HH; j++)
        s += g_hT[j * BB + b] * Wo[o * HH + j];
    out[b * OUTD + o] = s + bo[o];
}

extern "C" void kernel_launch(void* const* d_in, const int* in_sizes, int n_in,
                              void* d_out, int out_size) {
    const float* X  = (const float*)d_in[0];
    const float* Wx = (const float*)d_in[1];
    const float* bx = (const float*)d_in[2];
    const float* Wh = (const float*)d_in[3];
    const float* Uz = (const float*)d_in[4];
    const float* bz = (const float*)d_in[5];
    const float* Vz = (const float*)d_in[6];
    const float* Ur = (const float*)d_in[7];
    const float* br = (const float*)d_in[8];
    const float* Vr = (const float*)d_in[9];
    const float* Wo = (const float*)d_in[10];
    const float* bo = (const float*)d_in[11];
    float* out = (float*)d_out;

    const int scan_smem = (3 * 8192 + 2 * 8 * 512) * (int)sizeof(float);
    cudaFuncSetAttribute(scan_kernel, cudaFuncAttributeMaxDynamicSharedMemorySize, scan_smem);

    dim3 pg(HH / 64, TT, 3);
    proj_kernel<<<pg, 256>>>(X, Wx, Uz, Ur, bx, bz, br);
    scan_kernel<<<NCTA, 256, scan_smem>>>(Wh, Vz, Vr);
    out_kernel<<<OUTD / 4, 256>>>(Wo, bo, out);
}